// round 1
// baseline (speedup 1.0000x reference)
#include <cuda_runtime.h>
#include <cuda_bf16.h>
#include <math.h>
#include <stdint.h>

// Problem constants (fixed shapes for this bench)
#define BB 4
#define PP 256
#define CC 151
#define RTOT 51
#define RR 50                 // r = 1..50
#define CELLS (CC * RR)       // 7550 per direction
#define G2OFF CELLS           // G2 starts here
#define GPAD (2 * CELLS)      // 15100 : zero pad slot for vector-list padding
#define GTOT (GPAD + 4)       // 15104 floats
#define LSTRIDE 1600          // per-c list capacity (mean ~755, +31 sigma headroom)

// Static device scratch (no allocation allowed)
__device__ unsigned short g_list[CC * LSTRIDE];   // combined sparse lists per c
__device__ int            g_cnt[CC];              // padded (multiple of 8) list lengths
__device__ int            g_bstart[BB][CC + 1];   // label bucket offsets per image
__device__ int            g_perm[BB][PP];         // p's sorted by label per image
__device__ float          g_loss[BB * PP];        // per-(b,q) losses

// ---------------------------------------------------------------------------
// Kernel A: build per-c sparse (l,r) index lists from relationship_mat.
// Entry encodes smem index: part*7550 + l*50 + (r-1)  (< 15100, fits u16).
// Deterministic: chunked count -> prefix -> write.
// ---------------------------------------------------------------------------
__global__ void build_lists_kernel(const float* __restrict__ mat) {
    const int c = blockIdx.x;
    const int t = threadIdx.x;
    const int NITEMS = 2 * CELLS;                 // 15100
    const int ITEMS = (NITEMS + 255) / 256;       // 59

    __shared__ int sCnt[256];
    __shared__ int sBase[257];

    int k0 = t * ITEMS;
    int k1 = min(k0 + ITEMS, NITEMS);

    int cnt = 0;
    for (int k = k0; k < k1; k++) {
        int part = (k >= CELLS) ? 1 : 0;
        int j = k - part * CELLS;
        int l = j / RR, rr = j % RR;
        float v = part ? mat[(c * CC + l) * RTOT + rr + 1]
                       : mat[(l * CC + c) * RTOT + rr + 1];
        cnt += (v != 0.0f) ? 1 : 0;
    }
    sCnt[t] = cnt;
    __syncthreads();
    if (t == 0) {
        int s = 0;
        for (int i = 0; i < 256; i++) { sBase[i] = s; s += sCnt[i]; }
        sBase[256] = s;
    }
    __syncthreads();

    int pos = sBase[t];
    for (int k = k0; k < k1; k++) {
        int part = (k >= CELLS) ? 1 : 0;
        int j = k - part * CELLS;
        int l = j / RR, rr = j % RR;
        float v = part ? mat[(c * CC + l) * RTOT + rr + 1]
                       : mat[(l * CC + c) * RTOT + rr + 1];
        if (v != 0.0f) {
            if (pos < LSTRIDE)
                g_list[c * LSTRIDE + pos] = (unsigned short)(part * CELLS + j);
            pos++;
        }
    }
    __syncthreads();
    if (t == 0) {
        int n = sBase[256];
        if (n > LSTRIDE) n = LSTRIDE;
        int npad = (n + 7) & ~7;
        if (npad > LSTRIDE) npad = LSTRIDE & ~7;
        for (int i = n; i < npad; i++)
            g_list[c * LSTRIDE + i] = (unsigned short)GPAD;  // points at zero pad
        g_cnt[c] = npad;
    }
}

// ---------------------------------------------------------------------------
// Kernel B: per-image counting sort of p by label (deterministic, serial —
// trivial work: 4 images x 256 elements).
// ---------------------------------------------------------------------------
__global__ void build_buckets_kernel(const int* __restrict__ labels) {
    const int b = blockIdx.x;
    if (threadIdx.x != 0) return;
    int cnt[CC];
    for (int l = 0; l < CC; l++) cnt[l] = 0;
    for (int p = 0; p < PP; p++) cnt[labels[b * PP + p]]++;
    int s = 0;
    int ofs[CC];
    for (int l = 0; l < CC; l++) { g_bstart[b][l] = s; ofs[l] = s; s += cnt[l]; }
    g_bstart[b][CC] = s;  // == PP
    for (int p = 0; p < PP; p++) {
        int l = labels[b * PP + p];
        g_perm[b][ofs[l]++] = p;
    }
}

// ---------------------------------------------------------------------------
// Kernel C: main. One block per (b,q). Phase 1: bucketed aggregation of rel
// into G/G2 in smem (no atomics, each output cell written once). Phase 2:
// sparse gather-sum per c, then log-softmax + NLL.
// ---------------------------------------------------------------------------
extern __shared__ float dynsmem[];

__global__ __launch_bounds__(256) void main_kernel(const float* __restrict__ rel,
                                                   const int*  __restrict__ labels) {
    float* G      = dynsmem;                      // [GTOT]
    int*   sStart = (int*)(G + GTOT);             // [CC+1]
    int*   sPerm  = sStart + (CC + 1);            // [PP]
    int*   sLab   = sPerm + PP;                   // [PP]
    float* sTheta = (float*)(sLab + PP);          // [CC+1]
    float* sRed   = sTheta + (CC + 1);            // [16]

    const int b = blockIdx.x >> 8;
    const int q = blockIdx.x & 255;
    const int t = threadIdx.x;

    if (t < CC + 1) sStart[t] = g_bstart[b][t];
    sPerm[t] = g_perm[b][t];
    sLab[t]  = labels[b * PP + t];
    if (t < 4) G[GPAD + t] = 0.0f;
    __syncthreads();

    // Base addresses: rel[((b*PP+p)*PP+qq)*RTOT + r]
    const long colBase = ((long)(b * PP) * PP + q) * RTOT;     // + p*PP*RTOT + r
    const long rowBase = ((long)(b * PP + q)) * PP * RTOT;     // + p*RTOT   + r

    // Phase 1: one pass per cell (l, rr); lanes span consecutive rr -> coalesced.
    for (int j = t; j < CELLS; j += 256) {
        int l = j / RR, rr = j % RR;
        int s0 = sStart[l], s1 = sStart[l + 1];
        float sb = 0.0f, st = 0.0f;
        for (int i = s0; i < s1; i++) {
            int p = sPerm[i];
            sb += rel[colBase + (long)p * (PP * RTOT) + rr + 1];
            st += rel[rowBase + (long)p * RTOT + rr + 1];
        }
        G[j]         = sb;
        G[G2OFF + j] = st;
    }
    __syncthreads();

    // Diagonal correction: remove p == q contribution (r >= 1 only).
    if (t < RR) {
        float v = rel[rowBase + (long)q * RTOT + t + 1];
        int j = sLab[q] * RR + t;
        G[j]         -= v;
        G[G2OFF + j] -= v;
    }
    __syncthreads();

    // Phase 2: sparse gather-sum per class c = t.
    float theta = -INFINITY;
    if (t < CC) {
        int n = g_cnt[t];
        const uint4* lp = (const uint4*)&g_list[t * LSTRIDE];
        float a0 = 0.0f, a1 = 0.0f;
        int n8 = n >> 3;
        for (int i = 0; i < n8; i++) {
            uint4 v = lp[i];
            a0 += G[v.x & 0xFFFFu] + G[v.x >> 16];
            a1 += G[v.y & 0xFFFFu] + G[v.y >> 16];
            a0 += G[v.z & 0xFFFFu] + G[v.z >> 16];
            a1 += G[v.w & 0xFFFFu] + G[v.w >> 16];
        }
        theta = 0.25f * (a0 + a1);   // 0.5 * (b+t) with W=0.5 on r>=1
        sTheta[t] = theta;
    }

    // Block max
    float m = theta;
    #pragma unroll
    for (int o = 16; o; o >>= 1) m = fmaxf(m, __shfl_xor_sync(0xFFFFFFFFu, m, o));
    if ((t & 31) == 0) sRed[t >> 5] = m;
    __syncthreads();
    if (t == 0) {
        float mm = sRed[0];
        for (int i = 1; i < 8; i++) mm = fmaxf(mm, sRed[i]);
        sRed[8] = mm;
    }
    __syncthreads();
    m = sRed[8];

    // Block sum of exp
    float e = (t < CC) ? expf(theta - m) : 0.0f;
    #pragma unroll
    for (int o = 16; o; o >>= 1) e += __shfl_xor_sync(0xFFFFFFFFu, e, o);
    __syncthreads();   // sRed reuse
    if ((t & 31) == 0) sRed[t >> 5] = e;
    __syncthreads();
    if (t == 0) {
        float s = 0.0f;
        for (int i = 0; i < 8; i++) s += sRed[i];
        float lse = m + logf(s);
        g_loss[blockIdx.x] = lse - sTheta[sLab[q]];
    }
}

// ---------------------------------------------------------------------------
// Kernel D: deterministic mean over 1024 losses.
// ---------------------------------------------------------------------------
__global__ void reduce_loss_kernel(float* __restrict__ out) {
    __shared__ float s[256];
    int t = threadIdx.x;
    float a = g_loss[t] + g_loss[t + 256] + g_loss[t + 512] + g_loss[t + 768];
    s[t] = a;
    __syncthreads();
    for (int o = 128; o; o >>= 1) {
        if (t < o) s[t] += s[t + o];
        __syncthreads();
    }
    if (t == 0) out[0] = s[0] * (1.0f / 1024.0f);
}

// ---------------------------------------------------------------------------
extern "C" void kernel_launch(void* const* d_in, const int* in_sizes, int n_in,
                              void* d_out, int out_size) {
    // Identify inputs by element count (robust to ordering).
    const float* rel = nullptr;
    const float* mat = nullptr;
    const int*   lab = nullptr;
    for (int i = 0; i < n_in; i++) {
        switch (in_sizes[i]) {
            case BB * PP * PP * RTOT: rel = (const float*)d_in[i]; break;  // 13,369,344
            case CC * CC * RTOT:      mat = (const float*)d_in[i]; break;  // 1,162,701
            case BB * PP:             lab = (const int*)d_in[i];   break;  // 1,024
            default: break;  // roi_scores (unused), num_images (unused)
        }
    }

    const int smem_bytes = GTOT * 4 + (CC + 1) * 4 + PP * 4 + PP * 4 + (CC + 1) * 4 + 16 * 4;
    cudaFuncSetAttribute(main_kernel, cudaFuncAttributeMaxDynamicSharedMemorySize, smem_bytes);

    build_lists_kernel<<<CC, 256>>>(mat);
    build_buckets_kernel<<<BB, 32>>>(lab);
    main_kernel<<<BB * PP, 256, smem_bytes>>>(rel, lab);
    reduce_loss_kernel<<<1, 256>>>((float*)d_out);
}